// round 12
// baseline (speedup 1.0000x reference)
#include <cuda_runtime.h>
#include <cuda_bf16.h>
#include <math.h>
#include <stdint.h>

#define NN 50000
#define EE 800000
#define INC 256
#define HID 256
#define OUTC 128

#define GB 60              // gather blocks in fused kernel
#define TOTB 148           // total fused blocks (<= SM count)
#define GWORK ((TOTB - GB) / 2)   // 44 GEMM workers per column half

// ---------------- scratch (static device globals; no allocation) -------------
__device__ __nv_bfloat16 g_xhi[(size_t)NN * HID];
__device__ __nv_bfloat16 g_xlo[(size_t)NN * HID];
__device__ __nv_bfloat16 g_mhi[(size_t)NN * HID];
__device__ __nv_bfloat16 g_mlo[(size_t)NN * HID];
__device__ float g_h1[(size_t)NN * HID];
__device__ int   g_src[EE];
__device__ int   g_dst[EE];
__device__ int   g_col[EE];
__device__ int   g_deg[NN];
__device__ int   g_rowptr[NN + 1];
__device__ int   g_cursor[NN];
__device__ int   g_bsum[256];
__device__ int   g_boff[256];
__device__ int   g_is64;
__device__ int   g_flagA[512];
__device__ int   g_flagB[512];
__device__ __nv_bfloat16 g_wt_hi[4][256 * 256];
__device__ __nv_bfloat16 g_wt_lo[4][256 * 256];

// ---------------- helpers -----------------------------------------------------
__device__ __forceinline__ uint32_t smem_u32(const void* p) {
    uint32_t a;
    asm("{ .reg .u64 t; cvta.to.shared.u64 t, %1; cvt.u32.u64 %0, t; }" : "=r"(a) : "l"(p));
    return a;
}
__device__ __forceinline__ void ldsm_x4(uint32_t* r, uint32_t addr) {
    asm volatile("ldmatrix.sync.aligned.m8n8.x4.shared.b16 {%0,%1,%2,%3}, [%4];"
                 : "=r"(r[0]), "=r"(r[1]), "=r"(r[2]), "=r"(r[3]) : "r"(addr));
}
__device__ __forceinline__ void mma_bf16(float* d, const uint32_t* a, const uint32_t* b) {
    asm volatile(
        "mma.sync.aligned.m16n8k16.row.col.f32.bf16.bf16.f32 "
        "{%0,%1,%2,%3}, {%4,%5,%6,%7}, {%8,%9}, {%0,%1,%2,%3};"
        : "+f"(d[0]), "+f"(d[1]), "+f"(d[2]), "+f"(d[3])
        : "r"(a[0]), "r"(a[1]), "r"(a[2]), "r"(a[3]), "r"(b[0]), "r"(b[1]));
}
__device__ __forceinline__ void split1(float v, unsigned short& h, unsigned short& l) {
    __nv_bfloat16 bh = __float2bfloat16_rn(v);
    float r = v - __bfloat162float(bh);
    __nv_bfloat16 bl = __float2bfloat16_rn(r);
    h = __bfloat16_as_ushort(bh);
    l = __bfloat16_as_ushort(bl);
}
__device__ __forceinline__ void split4(float4 v, uint2& hh, uint2& ll) {
    unsigned short h[4], l[4];
    split1(v.x, h[0], l[0]); split1(v.y, h[1], l[1]);
    split1(v.z, h[2], l[2]); split1(v.w, h[3], l[3]);
    hh = make_uint2((uint32_t)h[0] | ((uint32_t)h[1] << 16),
                    (uint32_t)h[2] | ((uint32_t)h[3] << 16));
    ll = make_uint2((uint32_t)l[0] | ((uint32_t)l[1] << 16),
                    (uint32_t)l[2] | ((uint32_t)l[3] << 16));
}
__device__ __forceinline__ void add4(float4& a, float4 v) {
    a.x += v.x; a.y += v.y; a.z += v.z; a.w += v.w;
}

// ---------------- fused zero_deg + flags + edge dtype detection --------------
__global__ void detzero_k(const unsigned int* __restrict__ ei) {
    int i = blockIdx.x * blockDim.x + threadIdx.x;
    if (i < NN) g_deg[i] = 0;
    if (i < 512) { g_flagA[i] = 0; g_flagB[i] = 0; }
    if (blockIdx.x == 0 && threadIdx.x < 32) {
        unsigned v = ei[threadIdx.x * 2 + 1];
        unsigned nz = __ballot_sync(0xFFFFFFFFu, v != 0u);
        if (threadIdx.x == 0) g_is64 = (nz == 0u) ? 1 : 0;
    }
}

__global__ void decode_hist_k(const void* __restrict__ ei, int E) {
    int i = blockIdx.x * blockDim.x + threadIdx.x;
    if (i >= E) return;
    int s, d;
    if (g_is64) {
        const long long* p = (const long long*)ei;
        s = (int)p[i];
        d = (int)p[(size_t)E + i];
    } else {
        const int* p = (const int*)ei;
        s = p[i];
        d = p[E + i];
    }
    g_src[i] = s;
    g_dst[i] = d;
    atomicAdd(&g_deg[d], 1);
}

__global__ void block_sum_k(int n) {
    __shared__ int sh[8];
    int i = blockIdx.x * 256 + threadIdx.x;
    int lane = threadIdx.x & 31;
    int wid = threadIdx.x >> 5;
    int v = (i < n) ? g_deg[i] : 0;
#pragma unroll
    for (int o = 16; o; o >>= 1) v += __shfl_down_sync(0xFFFFFFFFu, v, o);
    if (lane == 0) sh[wid] = v;
    __syncthreads();
    if (threadIdx.x == 0) {
        int s = 0;
#pragma unroll
        for (int w = 0; w < 8; w++) s += sh[w];
        g_bsum[blockIdx.x] = s;
    }
}

__global__ void scan_bsums_k(int nb) {
    __shared__ int sh[256];
    int tid = threadIdx.x;
    int v = (tid < nb) ? g_bsum[tid] : 0;
    sh[tid] = v;
    __syncthreads();
    for (int off = 1; off < 256; off <<= 1) {
        int t = (tid >= off) ? sh[tid - off] : 0;
        __syncthreads();
        sh[tid] += t;
        __syncthreads();
    }
    g_boff[tid] = sh[tid] - v;
}

__global__ void rowptr_k(int n) {
    __shared__ int sh[256];
    int i = blockIdx.x * 256 + threadIdx.x;
    int tid = threadIdx.x;
    int v = (i < n) ? g_deg[i] : 0;
    sh[tid] = v;
    __syncthreads();
    for (int off = 1; off < 256; off <<= 1) {
        int t = (tid >= off) ? sh[tid - off] : 0;
        __syncthreads();
        sh[tid] += t;
        __syncthreads();
    }
    int ex = g_boff[blockIdx.x] + sh[tid] - v;
    if (i < n) {
        g_rowptr[i] = ex;
        g_cursor[i] = ex;
        if (i == n - 1) g_rowptr[n] = ex + v;
    }
}

__global__ void fill_k(int E) {
    int i = blockIdx.x * blockDim.x + threadIdx.x;
    if (i >= E) return;
    int d = g_dst[i];
    int pos = atomicAdd(&g_cursor[d], 1);
    g_col[pos] = g_src[i];
}

// ---------------- weight transpose + hi/lo split ------------------------------
__global__ void tw_all_k(const float* __restrict__ W0, const float* __restrict__ W1,
                         const float* __restrict__ W2, const float* __restrict__ W3) {
    int w = blockIdx.y;
    const float* W = (w == 0) ? W0 : (w == 1) ? W1 : (w == 2) ? W2 : W3;
    int Ncols = (w == 3) ? OUTC : HID;
    int id = blockIdx.x * 256 + threadIdx.x;
    if (id >= 256 * Ncols) return;
    int k = id / Ncols, n = id % Ncols;
    float v = W[id];
    unsigned short h, l;
    split1(v, h, l);
    g_wt_hi[w][(size_t)n * 256 + k] = __ushort_as_bfloat16(h);
    g_wt_lo[w][(size_t)n * 256 + k] = __ushort_as_bfloat16(l);
}

// ---------------- smem layout for GEMM role -----------------------------------
#define BSTR 528
#define ASTR 80
#define ASTAGE (2 * 128 * ASTR)
#define SM_BHI 0
#define SM_BLO (128 * BSTR)
#define SM_A   (2 * 128 * BSTR)
#define SM_TOTAL (SM_A + 3 * ASTAGE)

// ---------------- gather role: 4 concurrent nodes per warp --------------------
__device__ void gather_role(const float4* __restrict__ X, const float* __restrict__ eps,
                            __nv_bfloat16* __restrict__ Ohi, __nv_bfloat16* __restrict__ Olo,
                            int* __restrict__ flags, int M, int mtiles)
{
    const int tid = threadIdx.x;
    const int warp = tid >> 5, lane = tid & 31;
    const float alpha = 1.0f + *eps;

    for (int t = blockIdx.x; t < mtiles; t += GB) {
#pragma unroll 1
        for (int p = 0; p < 4; p++) {
            const int n0 = t * 128 + warp * 16 + p * 4;
            float4 acc[4][2];
            int beg[4], deg[4];
#pragma unroll
            for (int i = 0; i < 4; i++) {
                int n = n0 + i;
                int ok = (n < M);
                int b = ok ? g_rowptr[n] : 0;
                int e = ok ? g_rowptr[n + 1] : 0;
                beg[i] = b;
                deg[i] = e - b;
                acc[i][0] = make_float4(0.f, 0.f, 0.f, 0.f);
                acc[i][1] = make_float4(0.f, 0.f, 0.f, 0.f);
            }
            int mx = max(max(deg[0], deg[1]), max(deg[2], deg[3]));
#pragma unroll 1
            for (int j = 0; j < mx; j += 4) {
#pragma unroll
                for (int q = 0; q < 4; q++) {
#pragma unroll
                    for (int i = 0; i < 4; i++) {
                        if (j + q < deg[i]) {
                            int s = __ldg(&g_col[beg[i] + j + q]);
                            float4 v0 = X[(size_t)s * 64 + lane];
                            float4 v1 = X[(size_t)s * 64 + 32 + lane];
                            add4(acc[i][0], v0);
                            add4(acc[i][1], v1);
                        }
                    }
                }
            }
#pragma unroll
            for (int i = 0; i < 4; i++) {
                int n = n0 + i;
                if (n >= M) continue;
                float4 x0 = X[(size_t)n * 64 + lane];
                float4 x1 = X[(size_t)n * 64 + 32 + lane];
                acc[i][0].x = fmaf(alpha, x0.x, acc[i][0].x);
                acc[i][0].y = fmaf(alpha, x0.y, acc[i][0].y);
                acc[i][0].z = fmaf(alpha, x0.z, acc[i][0].z);
                acc[i][0].w = fmaf(alpha, x0.w, acc[i][0].w);
                acc[i][1].x = fmaf(alpha, x1.x, acc[i][1].x);
                acc[i][1].y = fmaf(alpha, x1.y, acc[i][1].y);
                acc[i][1].z = fmaf(alpha, x1.z, acc[i][1].z);
                acc[i][1].w = fmaf(alpha, x1.w, acc[i][1].w);
                uint2 h0, l0, h1, l1;
                split4(acc[i][0], h0, l0);
                split4(acc[i][1], h1, l1);
                size_t base = (size_t)n * 256 + 4 * lane;
                *(uint2*)(Ohi + base)       = h0;
                *(uint2*)(Olo + base)       = l0;
                *(uint2*)(Ohi + base + 128) = h1;
                *(uint2*)(Olo + base + 128) = l1;
            }
        }
        // release: all stores visible, then set flag
        __threadfence();
        __syncthreads();
        if (tid == 0) atomicExch(&flags[t], 1);
    }
}

// ---------------- GEMM role (persistent, flag-acquire per tile) ----------------
__device__ void gemm_role(char* smem, uint32_t sb,
                          const __nv_bfloat16* __restrict__ Ahi, const __nv_bfloat16* __restrict__ Alo,
                          const __nv_bfloat16* __restrict__ Whi, const __nv_bfloat16* __restrict__ Wlo,
                          const float* __restrict__ bias,
                          __nv_bfloat16* __restrict__ Chi, __nv_bfloat16* __restrict__ Clo,
                          int* __restrict__ flags, int M, int mtiles)
{
    const int tid = threadIdx.x;
    const int wid = tid >> 5, lane = tid & 31;
    const int gbid = blockIdx.x - GB;
    const int cb = gbid & 1;               // column half
    const int worker = gbid >> 1;          // 0..GWORK-1
    const int warp_m = wid & 3, warp_n = wid >> 2;
    const int Ncols = HID;

    // load B hi/lo once
    {
        const uint4* shp = (const uint4*)(Whi + (size_t)cb * 128 * 256);
        const uint4* slp = (const uint4*)(Wlo + (size_t)cb * 128 * 256);
        for (int f = tid; f < 4096; f += 256) {
            int n = f >> 5, kc = f & 31;
            *(uint4*)(smem + SM_BHI + n * BSTR + kc * 16) = shp[n * 32 + kc];
            *(uint4*)(smem + SM_BLO + n * BSTR + kc * 16) = slp[n * 32 + kc];
        }
    }

    const int colbase = cb * 128 + warp_n * 64;
    float bv0[8], bv1[8];
#pragma unroll
    for (int nf = 0; nf < 8; nf++) {
        int col = colbase + nf * 8 + (lane & 3) * 2;
        bv0[nf] = bias[col];
        bv1[nf] = bias[col + 1];
    }

    auto loadA = [&](int c, int st, int blockRow) {
        uint32_t base = sb + SM_A + st * ASTAGE;
#pragma unroll
        for (int j = 0; j < 2; j++) {
            int f = j * 256 + tid;
            int row = f >> 2;
            int seg = f & 3;
            int grow = blockRow + row;
            int ok = (grow < M);
            size_t off = (size_t)(ok ? grow : 0) * 256 + c * 32 + seg * 8;
            uint32_t dh = base + row * ASTR + seg * 16;
            uint32_t dl = dh + 128 * ASTR;
            int ss = ok ? 16 : 0;
            asm volatile("cp.async.ca.shared.global [%0], [%1], 16, %2;"
                         :: "r"(dh), "l"((const char*)(Ahi + off)), "r"(ss));
            asm volatile("cp.async.ca.shared.global [%0], [%1], 16, %2;"
                         :: "r"(dl), "l"((const char*)(Alo + off)), "r"(ss));
        }
        asm volatile("cp.async.commit_group;");
    };

    for (int tile = worker; tile < mtiles; tile += GWORK) {
        const int blockRow = tile * 128;

        // acquire tile flag
        if (tid == 0) {
            volatile int* f = (volatile int*)&flags[tile];
            while (*f == 0) { __nanosleep(64); }
            __threadfence();
        }
        __syncthreads();

        float acc[2][8][4];
#pragma unroll
        for (int mf = 0; mf < 2; mf++)
#pragma unroll
            for (int nf = 0; nf < 8; nf++)
#pragma unroll
                for (int q = 0; q < 4; q++) acc[mf][nf][q] = 0.f;

        loadA(0, 0, blockRow);
        loadA(1, 1, blockRow);

#pragma unroll
        for (int c = 0; c < 8; c++) {
            if (c + 1 < 8) {
                asm volatile("cp.async.wait_group 1;" ::: "memory");
            } else {
                asm volatile("cp.async.wait_group 0;" ::: "memory");
            }
            __syncthreads();

            const uint32_t abase = sb + SM_A + (c % 3) * ASTAGE;
#pragma unroll
            for (int s = 0; s < 2; s++) {
                const int k0 = s * 16;
                const int bk0 = c * 32 + k0;
                uint32_t ah[2][4], al[2][4];
#pragma unroll
                for (int mf = 0; mf < 2; mf++) {
                    int row = warp_m * 32 + mf * 16 + (lane & 15);
                    uint32_t addr = abase + row * ASTR + (k0 + (lane >> 4) * 8) * 2;
                    ldsm_x4(ah[mf], addr);
                    ldsm_x4(al[mf], addr + 128 * ASTR);
                }
                uint32_t bh[8][2], bl[8][2];
#pragma unroll
                for (int q = 0; q < 4; q++) {
                    int trow = lane & 7;
                    int tsel = lane >> 3;
                    int n = warp_n * 64 + q * 16 + trow + ((tsel >> 1) * 8);
                    int koff = (tsel & 1) * 8;
                    uint32_t addr = sb + SM_BHI + n * BSTR + (bk0 + koff) * 2;
                    uint32_t tr[4];
                    ldsm_x4(tr, addr);
                    bh[q * 2][0] = tr[0]; bh[q * 2][1] = tr[1];
                    bh[q * 2 + 1][0] = tr[2]; bh[q * 2 + 1][1] = tr[3];
                    ldsm_x4(tr, addr + (SM_BLO - SM_BHI));
                    bl[q * 2][0] = tr[0]; bl[q * 2][1] = tr[1];
                    bl[q * 2 + 1][0] = tr[2]; bl[q * 2 + 1][1] = tr[3];
                }
#pragma unroll
                for (int mf = 0; mf < 2; mf++)
#pragma unroll
                    for (int nf = 0; nf < 8; nf++) {
                        mma_bf16(acc[mf][nf], ah[mf], bh[nf]);
                        mma_bf16(acc[mf][nf], ah[mf], bl[nf]);
                        mma_bf16(acc[mf][nf], al[mf], bh[nf]);
                    }
            }
            if (c + 2 < 8) loadA(c + 2, (c + 2) % 3, blockRow);
        }

        // epilogue: bias + relu + split store
#pragma unroll
        for (int mf = 0; mf < 2; mf++) {
            int r0 = blockRow + warp_m * 32 + mf * 16 + (lane >> 2);
            int r1 = r0 + 8;
#pragma unroll
            for (int nf = 0; nf < 8; nf++) {
                int col = colbase + nf * 8 + (lane & 3) * 2;
                float o0 = fmaxf(acc[mf][nf][0] + bv0[nf], 0.f);
                float o1 = fmaxf(acc[mf][nf][1] + bv1[nf], 0.f);
                float o2 = fmaxf(acc[mf][nf][2] + bv0[nf], 0.f);
                float o3 = fmaxf(acc[mf][nf][3] + bv1[nf], 0.f);
                unsigned short h0, l0, h1, l1;
                if (r0 < M) {
                    split1(o0, h0, l0); split1(o1, h1, l1);
                    *(uint32_t*)(Chi + (size_t)r0 * Ncols + col) = (uint32_t)h0 | ((uint32_t)h1 << 16);
                    *(uint32_t*)(Clo + (size_t)r0 * Ncols + col) = (uint32_t)l0 | ((uint32_t)l1 << 16);
                }
                if (r1 < M) {
                    split1(o2, h0, l0); split1(o3, h1, l1);
                    *(uint32_t*)(Chi + (size_t)r1 * Ncols + col) = (uint32_t)h0 | ((uint32_t)h1 << 16);
                    *(uint32_t*)(Clo + (size_t)r1 * Ncols + col) = (uint32_t)l0 | ((uint32_t)l1 << 16);
                }
            }
        }
        __syncthreads();   // protect smem A ring before next tile's loads
    }
}

// ---------------- fused gather + GEMM1 kernel ----------------------------------
__global__ void __launch_bounds__(256, 1) fused_gg(
    const float4* __restrict__ X, const float* __restrict__ eps,
    const __nv_bfloat16* __restrict__ Whi, const __nv_bfloat16* __restrict__ Wlo,
    const float* __restrict__ bias,
    __nv_bfloat16* __restrict__ Ahi, __nv_bfloat16* __restrict__ Alo,
    __nv_bfloat16* __restrict__ Chi, __nv_bfloat16* __restrict__ Clo,
    int* flags, int M, int mtiles)
{
    extern __shared__ char smem[];
    if (blockIdx.x < GB) {
        gather_role(X, eps, Ahi, Alo, flags, M, mtiles);
    } else {
        gemm_role(smem, smem_u32(smem), Ahi, Alo, Whi, Wlo, bias, Chi, Clo, flags, M, mtiles);
    }
}

// ---------------- standalone persistent GEMM (unchanged structure) -------------
template <int RELU, int SPLIT, int LSM>
__global__ void __launch_bounds__(256, 1) gemm_mma(
    const __nv_bfloat16* __restrict__ Ahi, const __nv_bfloat16* __restrict__ Alo,
    const __nv_bfloat16* __restrict__ Whi, const __nv_bfloat16* __restrict__ Wlo,
    const float* __restrict__ bias,
    float* __restrict__ C,
    __nv_bfloat16* __restrict__ Chi, __nv_bfloat16* __restrict__ Clo,
    int M, int Ncols, int mtiles)
{
    extern __shared__ char smem[];
    const uint32_t sb = smem_u32(smem);
    const int tid = threadIdx.x;
    const int wid = tid >> 5, lane = tid & 31;
    const int cb = blockIdx.y;
    const int warp_m = wid & 3, warp_n = wid >> 2;

    {
        const uint4* shp = (const uint4*)(Whi + (size_t)cb * 128 * 256);
        const uint4* slp = (const uint4*)(Wlo + (size_t)cb * 128 * 256);
        for (int f = tid; f < 4096; f += 256) {
            int n = f >> 5, kc = f & 31;
            *(uint4*)(smem + SM_BHI + n * BSTR + kc * 16) = shp[n * 32 + kc];
            *(uint4*)(smem + SM_BLO + n * BSTR + kc * 16) = slp[n * 32 + kc];
        }
    }

    const int colbase = cb * 128 + warp_n * 64;
    float bv0[8], bv1[8];
#pragma unroll
    for (int nf = 0; nf < 8; nf++) {
        int col = colbase + nf * 8 + (lane & 3) * 2;
        bv0[nf] = bias[col];
        bv1[nf] = bias[col + 1];
    }

    auto loadA = [&](int c, int st, int blockRow) {
        uint32_t base = sb + SM_A + st * ASTAGE;
#pragma unroll
        for (int j = 0; j < 2; j++) {
            int f = j * 256 + tid;
            int row = f >> 2;
            int seg = f & 3;
            int grow = blockRow + row;
            int ok = (grow < M);
            size_t off = (size_t)(ok ? grow : 0) * 256 + c * 32 + seg * 8;
            uint32_t dh = base + row * ASTR + seg * 16;
            uint32_t dl = dh + 128 * ASTR;
            int ss = ok ? 16 : 0;
            asm volatile("cp.async.ca.shared.global [%0], [%1], 16, %2;"
                         :: "r"(dh), "l"((const char*)(Ahi + off)), "r"(ss));
            asm volatile("cp.async.ca.shared.global [%0], [%1], 16, %2;"
                         :: "r"(dl), "l"((const char*)(Alo + off)), "r"(ss));
        }
        asm volatile("cp.async.commit_group;");
    };

    for (int tile = blockIdx.x; tile < mtiles; tile += gridDim.x) {
        const int blockRow = tile * 128;
        __syncthreads();

        float acc[2][8][4];
#pragma unroll
        for (int mf = 0; mf < 2; mf++)
#pragma unroll
            for (int nf = 0; nf < 8; nf++)
#pragma unroll
                for (int q = 0; q < 4; q++) acc[mf][nf][q] = 0.f;

        loadA(0, 0, blockRow);
        loadA(1, 1, blockRow);

#pragma unroll
        for (int c = 0; c < 8; c++) {
            if (c + 1 < 8) {
                asm volatile("cp.async.wait_group 1;" ::: "memory");
            } else {
                asm volatile("cp.async.wait_group 0;" ::: "memory");
            }
            __syncthreads();

            const uint32_t abase = sb + SM_A + (c % 3) * ASTAGE;
#pragma unroll
            for (int s = 0; s < 2; s++) {
                const int k0 = s * 16;
                const int bk0 = c * 32 + k0;
                uint32_t ah[2][4], al[2][4];
#pragma unroll
                for (int mf = 0; mf < 2; mf++) {
                    int row = warp_m * 32 + mf * 16 + (lane & 15);
                    uint32_t addr = abase + row * ASTR + (k0 + (lane >> 4) * 8) * 2;
                    ldsm_x4(ah[mf], addr);
                    ldsm_x4(al[mf], addr + 128 * ASTR);
                }
                uint32_t bh[8][2], bl[8][2];
#pragma unroll
                for (int q = 0; q < 4; q++) {
                    int trow = lane & 7;
                    int tsel = lane >> 3;
                    int n = warp_n * 64 + q * 16 + trow + ((tsel >> 1) * 8);
                    int koff = (tsel & 1) * 8;
                    uint32_t addr = sb + SM_BHI + n * BSTR + (bk0 + koff) * 2;
                    uint32_t tr[4];
                    ldsm_x4(tr, addr);
                    bh[q * 2][0] = tr[0]; bh[q * 2][1] = tr[1];
                    bh[q * 2 + 1][0] = tr[2]; bh[q * 2 + 1][1] = tr[3];
                    ldsm_x4(tr, addr + (SM_BLO - SM_BHI));
                    bl[q * 2][0] = tr[0]; bl[q * 2][1] = tr[1];
                    bl[q * 2 + 1][0] = tr[2]; bl[q * 2 + 1][1] = tr[3];
                }
#pragma unroll
                for (int mf = 0; mf < 2; mf++)
#pragma unroll
                    for (int nf = 0; nf < 8; nf++) {
                        mma_bf16(acc[mf][nf], ah[mf], bh[nf]);
                        mma_bf16(acc[mf][nf], ah[mf], bl[nf]);
                        mma_bf16(acc[mf][nf], al[mf], bh[nf]);
                    }
            }
            if (c + 2 < 8) loadA(c + 2, (c + 2) % 3, blockRow);
        }

#pragma unroll
        for (int mf = 0; mf < 2; mf++)
#pragma unroll
            for (int nf = 0; nf < 8; nf++) {
                acc[mf][nf][0] += bv0[nf]; acc[mf][nf][1] += bv1[nf];
                acc[mf][nf][2] += bv0[nf]; acc[mf][nf][3] += bv1[nf];
            }

        if (LSM) {
            float* sm_max = (float*)(smem + SM_A);
            float* sm_sum = (float*)(smem + SM_A + 1024);
            float mx[2][2], Mv[2][2], sv[2][2];
#pragma unroll
            for (int mf = 0; mf < 2; mf++)
#pragma unroll
                for (int ri = 0; ri < 2; ri++) {
                    float m = -1e30f;
#pragma unroll
                    for (int nf = 0; nf < 8; nf++) {
                        m = fmaxf(m, acc[mf][nf][ri * 2]);
                        m = fmaxf(m, acc[mf][nf][ri * 2 + 1]);
                    }
                    m = fmaxf(m, __shfl_xor_sync(0xFFFFFFFFu, m, 1));
                    m = fmaxf(m, __shfl_xor_sync(0xFFFFFFFFu, m, 2));
                    mx[mf][ri] = m;
                }
            if ((lane & 3) == 0) {
#pragma unroll
                for (int mf = 0; mf < 2; mf++)
#pragma unroll
                    for (int ri = 0; ri < 2; ri++) {
                        int rowl = warp_m * 32 + mf * 16 + ri * 8 + (lane >> 2);
                        sm_max[rowl * 2 + warp_n] = mx[mf][ri];
                    }
            }
            __syncthreads();
#pragma unroll
            for (int mf = 0; mf < 2; mf++)
#pragma unroll
                for (int ri = 0; ri < 2; ri++) {
                    int rowl = warp_m * 32 + mf * 16 + ri * 8 + (lane >> 2);
                    float m = fmaxf(sm_max[rowl * 2], sm_max[rowl * 2 + 1]);
                    Mv[mf][ri] = m;
                    float s = 0.f;
#pragma unroll
                    for (int nf = 0; nf < 8; nf++)
                        s += expf(acc[mf][nf][ri * 2] - m) + expf(acc[mf][nf][ri * 2 + 1] - m);
                    s += __shfl_xor_sync(0xFFFFFFFFu, s, 1);
                    s += __shfl_xor_sync(0xFFFFFFFFu, s, 2);
                    sv[mf][ri] = s;
                }
            if ((lane & 3) == 0) {
#pragma unroll
                for (int mf = 0; mf < 2; mf++)
#pragma unroll
                    for (int ri = 0; ri < 2; ri++) {
                        int rowl = warp_m * 32 + mf * 16 + ri * 8 + (lane >> 2);
                        sm_sum[rowl * 2 + warp_n] = sv[mf][ri];
                    }
            }
            __syncthreads();
#pragma unroll
            for (int mf = 0; mf < 2; mf++)
#pragma unroll
                for (int ri = 0; ri < 2; ri++) {
                    int rowl = warp_m * 32 + mf * 16 + ri * 8 + (lane >> 2);
                    float S = sm_sum[rowl * 2] + sm_sum[rowl * 2 + 1];
                    float lg = Mv[mf][ri] + logf(S);
                    int row = blockRow + rowl;
                    if (row < M) {
#pragma unroll
                        for (int nf = 0; nf < 8; nf++) {
                            int col = colbase + nf * 8 + (lane & 3) * 2;
                            *(float2*)(C + (size_t)row * Ncols + col) =
                                make_float2(acc[mf][nf][ri * 2] - lg, acc[mf][nf][ri * 2 + 1] - lg);
                        }
                    }
                }
        } else {
#pragma unroll
            for (int mf = 0; mf < 2; mf++) {
                int r0 = blockRow + warp_m * 32 + mf * 16 + (lane >> 2);
                int r1 = r0 + 8;
#pragma unroll
                for (int nf = 0; nf < 8; nf++) {
                    int col = colbase + nf * 8 + (lane & 3) * 2;
                    float o0 = acc[mf][nf][0], o1 = acc[mf][nf][1];
                    float o2 = acc[mf][nf][2], o3 = acc[mf][nf][3];
                    if (RELU) {
                        o0 = fmaxf(o0, 0.f); o1 = fmaxf(o1, 0.f);
                        o2 = fmaxf(o2, 0.f); o3 = fmaxf(o3, 0.f);
                    }
                    if (r0 < M) *(float2*)(C + (size_t)r0 * Ncols + col) = make_float2(o0, o1);
                    if (r1 < M) *(float2*)(C + (size_t)r1 * Ncols + col) = make_float2(o2, o3);
                }
            }
        }
    }
}

// ---------------- host launch -------------------------------------------------
extern "C" void kernel_launch(void* const* d_in, const int* in_sizes, int n_in,
                              void* d_out, int out_size) {
    const float* x    = (const float*)d_in[0];
    const void*  ei   = d_in[1];
    const float* eps0 = (const float*)d_in[2];
    const float* W1_0 = (const float*)d_in[3];
    const float* b1_0 = (const float*)d_in[4];
    const float* W2_0 = (const float*)d_in[5];
    const float* b2_0 = (const float*)d_in[6];
    const float* eps1 = (const float*)d_in[7];
    const float* W1_1 = (const float*)d_in[8];
    const float* b1_1 = (const float*)d_in[9];
    const float* W2_1 = (const float*)d_in[10];
    const float* b2_1 = (const float*)d_in[11];
    float* out = (float*)d_out;

    int E = in_sizes[1] / 2;
    if (E > EE) E = EE;
    int M = in_sizes[0] / INC;
    if (M > NN) M = NN;

    __nv_bfloat16 *xhi, *xlo, *mhi, *mlo, *whi, *wlo;
    float* h1;
    int *flagA, *flagB;
    cudaGetSymbolAddress((void**)&xhi, g_xhi);
    cudaGetSymbolAddress((void**)&xlo, g_xlo);
    cudaGetSymbolAddress((void**)&mhi, g_mhi);
    cudaGetSymbolAddress((void**)&mlo, g_mlo);
    cudaGetSymbolAddress((void**)&h1,  g_h1);
    cudaGetSymbolAddress((void**)&whi, g_wt_hi);
    cudaGetSymbolAddress((void**)&wlo, g_wt_lo);
    cudaGetSymbolAddress((void**)&flagA, g_flagA);
    cudaGetSymbolAddress((void**)&flagB, g_flagB);

    cudaFuncSetAttribute(fused_gg, cudaFuncAttributeMaxDynamicSharedMemorySize, SM_TOTAL);
    cudaFuncSetAttribute(gemm_mma<1, 0, 0>, cudaFuncAttributeMaxDynamicSharedMemorySize, SM_TOTAL);
    cudaFuncSetAttribute(gemm_mma<0, 0, 1>, cudaFuncAttributeMaxDynamicSharedMemorySize, SM_TOTAL);

    const int egrid = (E + 255) / 256;
    const int ngrid = (M + 255) / 256;
    const int mtiles = (M + 127) / 128;
    const dim3 grid_h(74, 2);
    const dim3 grid_o(148, 1);
    const int WSZ = 256 * 256;

    // ---- CSR build ----
    detzero_k<<<ngrid, 256>>>((const unsigned int*)ei);
    decode_hist_k<<<egrid, 256>>>(ei, E);
    block_sum_k<<<ngrid, 256>>>(M);
    scan_bsums_k<<<1, 256>>>(ngrid);
    rowptr_k<<<ngrid, 256>>>(M);
    fill_k<<<egrid, 256>>>(E);

    // ---- weight transpose + split ----
    tw_all_k<<<dim3(256, 4), 256>>>(W1_0, W2_0, W1_1, W2_1);

    // ---- layer 0: fused gather+GEMM1, then GEMM2 ----
    fused_gg<<<TOTB, 256, SM_TOTAL>>>((const float4*)x, eps0, whi + 0 * WSZ, wlo + 0 * WSZ,
                                      b1_0, xhi, xlo, mhi, mlo, flagA, M, mtiles);
    gemm_mma<1, 0, 0><<<grid_h, 256, SM_TOTAL>>>(mhi, mlo, whi + 1 * WSZ, wlo + 1 * WSZ,
                                                 b2_0, h1, nullptr, nullptr, M, HID, mtiles);

    // ---- layer 1: fused gather+GEMM3, then GEMM4 + log_softmax ----
    fused_gg<<<TOTB, 256, SM_TOTAL>>>((const float4*)h1, eps1, whi + 2 * WSZ, wlo + 2 * WSZ,
                                      b1_1, xhi, xlo, mhi, mlo, flagB, M, mtiles);
    gemm_mma<0, 0, 1><<<grid_o, 256, SM_TOTAL>>>(mhi, mlo, whi + 3 * WSZ, wlo + 3 * WSZ,
                                                 b2_1, out, nullptr, nullptr, M, OUTC, mtiles);
}

// round 14
// speedup vs baseline: 2.0643x; 2.0643x over previous
#include <cuda_runtime.h>
#include <cuda_bf16.h>
#include <math.h>
#include <stdint.h>

#define NN 50000
#define EE 800000
#define INC 256
#define HID 256
#define OUTC 128

// ---------------- scratch (static device globals; no allocation) -------------
__device__ __nv_bfloat16 g_xhi[(size_t)NN * HID];  // split of gather output
__device__ __nv_bfloat16 g_xlo[(size_t)NN * HID];
__device__ __nv_bfloat16 g_mhi[(size_t)NN * HID];  // split of MLP hidden
__device__ __nv_bfloat16 g_mlo[(size_t)NN * HID];
__device__ float g_h1[(size_t)NN * HID];           // layer-0 output (fp32)
__device__ int   g_src[EE];
__device__ int   g_dst[EE];
__device__ int   g_col[EE];
__device__ int   g_deg[NN];
__device__ int   g_rowptr[NN + 1];
__device__ int   g_cursor[NN];
__device__ int   g_bsum[256];
__device__ int   g_boff[256];
__device__ int   g_is64;
// transposed + hi/lo split weights: Wt[n][k] bf16
__device__ __nv_bfloat16 g_wt_hi[4][256 * 256];
__device__ __nv_bfloat16 g_wt_lo[4][256 * 256];

// ---------------- helpers -----------------------------------------------------
__device__ __forceinline__ uint32_t smem_u32(const void* p) {
    uint32_t a;
    asm("{ .reg .u64 t; cvta.to.shared.u64 t, %1; cvt.u32.u64 %0, t; }" : "=r"(a) : "l"(p));
    return a;
}
__device__ __forceinline__ void ldsm_x4(uint32_t* r, uint32_t addr) {
    asm volatile("ldmatrix.sync.aligned.m8n8.x4.shared.b16 {%0,%1,%2,%3}, [%4];"
                 : "=r"(r[0]), "=r"(r[1]), "=r"(r[2]), "=r"(r[3]) : "r"(addr));
}
__device__ __forceinline__ void mma_bf16(float* d, const uint32_t* a, const uint32_t* b) {
    asm volatile(
        "mma.sync.aligned.m16n8k16.row.col.f32.bf16.bf16.f32 "
        "{%0,%1,%2,%3}, {%4,%5,%6,%7}, {%8,%9}, {%0,%1,%2,%3};"
        : "+f"(d[0]), "+f"(d[1]), "+f"(d[2]), "+f"(d[3])
        : "r"(a[0]), "r"(a[1]), "r"(a[2]), "r"(a[3]), "r"(b[0]), "r"(b[1]));
}
__device__ __forceinline__ void split1(float v, unsigned short& h, unsigned short& l) {
    __nv_bfloat16 bh = __float2bfloat16_rn(v);
    float r = v - __bfloat162float(bh);
    __nv_bfloat16 bl = __float2bfloat16_rn(r);
    h = __bfloat16_as_ushort(bh);
    l = __bfloat16_as_ushort(bl);
}
__device__ __forceinline__ void split4(float4 v, uint2& hh, uint2& ll) {
    unsigned short h[4], l[4];
    split1(v.x, h[0], l[0]); split1(v.y, h[1], l[1]);
    split1(v.z, h[2], l[2]); split1(v.w, h[3], l[3]);
    hh = make_uint2((uint32_t)h[0] | ((uint32_t)h[1] << 16),
                    (uint32_t)h[2] | ((uint32_t)h[3] << 16));
    ll = make_uint2((uint32_t)l[0] | ((uint32_t)l[1] << 16),
                    (uint32_t)l[2] | ((uint32_t)l[3] << 16));
}
__device__ __forceinline__ void add4(float4& a, float4 v) {
    a.x += v.x; a.y += v.y; a.z += v.z; a.w += v.w;
}

// ---------------- fused zero_deg + edge dtype detection ----------------------
__global__ void detzero_k(const unsigned int* __restrict__ ei) {
    int i = blockIdx.x * blockDim.x + threadIdx.x;
    if (i < NN) g_deg[i] = 0;
    if (blockIdx.x == 0 && threadIdx.x < 32) {
        unsigned v = ei[threadIdx.x * 2 + 1];
        unsigned nz = __ballot_sync(0xFFFFFFFFu, v != 0u);
        if (threadIdx.x == 0) g_is64 = (nz == 0u) ? 1 : 0;
    }
}

__global__ void decode_hist_k(const void* __restrict__ ei, int E) {
    int i = blockIdx.x * blockDim.x + threadIdx.x;
    if (i >= E) return;
    int s, d;
    if (g_is64) {
        const long long* p = (const long long*)ei;
        s = (int)p[i];
        d = (int)p[(size_t)E + i];
    } else {
        const int* p = (const int*)ei;
        s = p[i];
        d = p[E + i];
    }
    g_src[i] = s;
    g_dst[i] = d;
    atomicAdd(&g_deg[d], 1);
}

__global__ void block_sum_k(int n) {
    __shared__ int sh[8];
    int i = blockIdx.x * 256 + threadIdx.x;
    int lane = threadIdx.x & 31;
    int wid = threadIdx.x >> 5;
    int v = (i < n) ? g_deg[i] : 0;
#pragma unroll
    for (int o = 16; o; o >>= 1) v += __shfl_down_sync(0xFFFFFFFFu, v, o);
    if (lane == 0) sh[wid] = v;
    __syncthreads();
    if (threadIdx.x == 0) {
        int s = 0;
#pragma unroll
        for (int w = 0; w < 8; w++) s += sh[w];
        g_bsum[blockIdx.x] = s;
    }
}

__global__ void scan_bsums_k(int nb) {
    __shared__ int sh[256];
    int tid = threadIdx.x;
    int v = (tid < nb) ? g_bsum[tid] : 0;
    sh[tid] = v;
    __syncthreads();
    for (int off = 1; off < 256; off <<= 1) {
        int t = (tid >= off) ? sh[tid - off] : 0;
        __syncthreads();
        sh[tid] += t;
        __syncthreads();
    }
    g_boff[tid] = sh[tid] - v;
}

__global__ void rowptr_k(int n) {
    __shared__ int sh[256];
    int i = blockIdx.x * 256 + threadIdx.x;
    int tid = threadIdx.x;
    int v = (i < n) ? g_deg[i] : 0;
    sh[tid] = v;
    __syncthreads();
    for (int off = 1; off < 256; off <<= 1) {
        int t = (tid >= off) ? sh[tid - off] : 0;
        __syncthreads();
        sh[tid] += t;
        __syncthreads();
    }
    int ex = g_boff[blockIdx.x] + sh[tid] - v;
    if (i < n) {
        g_rowptr[i] = ex;
        g_cursor[i] = ex;
        if (i == n - 1) g_rowptr[n] = ex + v;
    }
}

__global__ void fill_k(int E) {
    int i = blockIdx.x * blockDim.x + threadIdx.x;
    if (i >= E) return;
    int d = g_dst[i];
    int pos = atomicAdd(&g_cursor[d], 1);
    g_col[pos] = g_src[i];
}

// ---------------- weight transpose + hi/lo split (all 4 in one launch) -------
__global__ void tw_all_k(const float* __restrict__ W0, const float* __restrict__ W1,
                         const float* __restrict__ W2, const float* __restrict__ W3) {
    int w = blockIdx.y;
    const float* W = (w == 0) ? W0 : (w == 1) ? W1 : (w == 2) ? W2 : W3;
    int Ncols = (w == 3) ? OUTC : HID;
    int id = blockIdx.x * 256 + threadIdx.x;
    if (id >= 256 * Ncols) return;
    int k = id / Ncols, n = id % Ncols;
    float v = W[id];
    unsigned short h, l;
    split1(v, h, l);
    g_wt_hi[w][(size_t)n * 256 + k] = __ushort_as_bfloat16(h);
    g_wt_lo[w][(size_t)n * 256 + k] = __ushort_as_bfloat16(l);
}

// ---------------- gather: warp per node, 4-edge unroll, split bf16 output -----
__global__ __launch_bounds__(256) void gather_k(
    const float4* __restrict__ X, const float* __restrict__ eps,
    __nv_bfloat16* __restrict__ Ohi, __nv_bfloat16* __restrict__ Olo, int M)
{
    int warp = (blockIdx.x * blockDim.x + threadIdx.x) >> 5;
    int lane = threadIdx.x & 31;
    if (warp >= M) return;
    const float alpha = 1.0f + *eps;

    float4 a0 = make_float4(0.f, 0.f, 0.f, 0.f);
    float4 a1 = make_float4(0.f, 0.f, 0.f, 0.f);

    int beg = g_rowptr[warp];
    int end = g_rowptr[warp + 1];
    int e = beg;
    // 4-edge unroll: 8 independent float4 loads in flight
    for (; e + 3 < end; e += 4) {
        int s0 = __ldg(&g_col[e]);
        int s1 = __ldg(&g_col[e + 1]);
        int s2 = __ldg(&g_col[e + 2]);
        int s3 = __ldg(&g_col[e + 3]);
        float4 v00 = X[(size_t)s0 * 64 + lane];
        float4 v01 = X[(size_t)s0 * 64 + 32 + lane];
        float4 v10 = X[(size_t)s1 * 64 + lane];
        float4 v11 = X[(size_t)s1 * 64 + 32 + lane];
        float4 v20 = X[(size_t)s2 * 64 + lane];
        float4 v21 = X[(size_t)s2 * 64 + 32 + lane];
        float4 v30 = X[(size_t)s3 * 64 + lane];
        float4 v31 = X[(size_t)s3 * 64 + 32 + lane];
        add4(a0, v00); add4(a1, v01);
        add4(a0, v10); add4(a1, v11);
        add4(a0, v20); add4(a1, v21);
        add4(a0, v30); add4(a1, v31);
    }
    for (; e < end; e++) {
        int s0 = __ldg(&g_col[e]);
        float4 v00 = X[(size_t)s0 * 64 + lane];
        float4 v01 = X[(size_t)s0 * 64 + 32 + lane];
        add4(a0, v00); add4(a1, v01);
    }

    float4 x0 = X[(size_t)warp * 64 + lane];
    float4 x1 = X[(size_t)warp * 64 + 32 + lane];
    a0.x = fmaf(alpha, x0.x, a0.x); a0.y = fmaf(alpha, x0.y, a0.y);
    a0.z = fmaf(alpha, x0.z, a0.z); a0.w = fmaf(alpha, x0.w, a0.w);
    a1.x = fmaf(alpha, x1.x, a1.x); a1.y = fmaf(alpha, x1.y, a1.y);
    a1.z = fmaf(alpha, x1.z, a1.z); a1.w = fmaf(alpha, x1.w, a1.w);

    uint2 h0, l0, h1v, l1v;
    split4(a0, h0, l0);
    split4(a1, h1v, l1v);
    size_t base = (size_t)warp * 256 + 4 * lane;
    *(uint2*)(Ohi + base)       = h0;
    *(uint2*)(Olo + base)       = l0;
    *(uint2*)(Ohi + base + 128) = h1v;
    *(uint2*)(Olo + base + 128) = l1v;
}

// ---------------- persistent mma.sync bf16 hi/lo GEMM -------------------------
#define BSTR 528
#define ASTR 80
#define ASTAGE (2 * 128 * ASTR)
#define SM_BHI 0
#define SM_BLO (128 * BSTR)
#define SM_A   (2 * 128 * BSTR)
#define SM_TOTAL (SM_A + 3 * ASTAGE)

template <int RELU, int SPLIT, int LSM>
__global__ void __launch_bounds__(256, 1) gemm_mma(
    const __nv_bfloat16* __restrict__ Ahi, const __nv_bfloat16* __restrict__ Alo,
    const __nv_bfloat16* __restrict__ Whi, const __nv_bfloat16* __restrict__ Wlo,
    const float* __restrict__ bias,
    float* __restrict__ C,
    __nv_bfloat16* __restrict__ Chi, __nv_bfloat16* __restrict__ Clo,
    int M, int Ncols, int mtiles)
{
    extern __shared__ char smem[];
    const uint32_t sb = smem_u32(smem);
    const int tid = threadIdx.x;
    const int wid = tid >> 5, lane = tid & 31;
    const int cb = blockIdx.y;
    const int warp_m = wid & 3, warp_n = wid >> 2;

    // ---- load B hi/lo once ----
    {
        const uint4* shp = (const uint4*)(Whi + (size_t)cb * 128 * 256);
        const uint4* slp = (const uint4*)(Wlo + (size_t)cb * 128 * 256);
        for (int f = tid; f < 4096; f += 256) {
            int n = f >> 5, kc = f & 31;
            *(uint4*)(smem + SM_BHI + n * BSTR + kc * 16) = shp[n * 32 + kc];
            *(uint4*)(smem + SM_BLO + n * BSTR + kc * 16) = slp[n * 32 + kc];
        }
    }

    const int colbase = cb * 128 + warp_n * 64;
    float bv0[8], bv1[8];
#pragma unroll
    for (int nf = 0; nf < 8; nf++) {
        int col = colbase + nf * 8 + (lane & 3) * 2;
        bv0[nf] = bias[col];
        bv1[nf] = bias[col + 1];
    }

    auto loadA = [&](int c, int st, int blockRow) {
        uint32_t base = sb + SM_A + st * ASTAGE;
#pragma unroll
        for (int j = 0; j < 2; j++) {
            int f = j * 256 + tid;
            int row = f >> 2;
            int seg = f & 3;
            int grow = blockRow + row;
            int ok = (grow < M);
            size_t off = (size_t)(ok ? grow : 0) * 256 + c * 32 + seg * 8;
            uint32_t dh = base + row * ASTR + seg * 16;
            uint32_t dl = dh + 128 * ASTR;
            int ss = ok ? 16 : 0;
            asm volatile("cp.async.ca.shared.global [%0], [%1], 16, %2;"
                         :: "r"(dh), "l"((const char*)(Ahi + off)), "r"(ss));
            asm volatile("cp.async.ca.shared.global [%0], [%1], 16, %2;"
                         :: "r"(dl), "l"((const char*)(Alo + off)), "r"(ss));
        }
        asm volatile("cp.async.commit_group;");
    };

    for (int tile = blockIdx.x; tile < mtiles; tile += gridDim.x) {
        const int blockRow = tile * 128;
        __syncthreads();

        float acc[2][8][4];
#pragma unroll
        for (int mf = 0; mf < 2; mf++)
#pragma unroll
            for (int nf = 0; nf < 8; nf++)
#pragma unroll
                for (int q = 0; q < 4; q++) acc[mf][nf][q] = 0.f;

        loadA(0, 0, blockRow);
        loadA(1, 1, blockRow);

#pragma unroll
        for (int c = 0; c < 8; c++) {
            if (c + 1 < 8) {
                asm volatile("cp.async.wait_group 1;" ::: "memory");
            } else {
                asm volatile("cp.async.wait_group 0;" ::: "memory");
            }
            __syncthreads();

            const uint32_t abase = sb + SM_A + (c % 3) * ASTAGE;
#pragma unroll
            for (int s = 0; s < 2; s++) {
                const int k0 = s * 16;
                const int bk0 = c * 32 + k0;
                uint32_t ah[2][4], al[2][4];
#pragma unroll
                for (int mf = 0; mf < 2; mf++) {
                    int row = warp_m * 32 + mf * 16 + (lane & 15);
                    uint32_t addr = abase + row * ASTR + (k0 + (lane >> 4) * 8) * 2;
                    ldsm_x4(ah[mf], addr);
                    ldsm_x4(al[mf], addr + 128 * ASTR);
                }
                uint32_t bh[8][2], bl[8][2];
#pragma unroll
                for (int q = 0; q < 4; q++) {
                    int trow = lane & 7;
                    int tsel = lane >> 3;
                    int n = warp_n * 64 + q * 16 + trow + ((tsel >> 1) * 8);
                    int koff = (tsel & 1) * 8;
                    uint32_t addr = sb + SM_BHI + n * BSTR + (bk0 + koff) * 2;
                    uint32_t tr[4];
                    ldsm_x4(tr, addr);
                    bh[q * 2][0] = tr[0]; bh[q * 2][1] = tr[1];
                    bh[q * 2 + 1][0] = tr[2]; bh[q * 2 + 1][1] = tr[3];
                    ldsm_x4(tr, addr + (SM_BLO - SM_BHI));
                    bl[q * 2][0] = tr[0]; bl[q * 2][1] = tr[1];
                    bl[q * 2 + 1][0] = tr[2]; bl[q * 2 + 1][1] = tr[3];
                }
#pragma unroll
                for (int mf = 0; mf < 2; mf++)
#pragma unroll
                    for (int nf = 0; nf < 8; nf++) {
                        mma_bf16(acc[mf][nf], ah[mf], bh[nf]);
                        mma_bf16(acc[mf][nf], ah[mf], bl[nf]);
                        mma_bf16(acc[mf][nf], al[mf], bh[nf]);
                    }
            }
            if (c + 2 < 8) loadA(c + 2, (c + 2) % 3, blockRow);
        }

        // ---- add bias into acc ----
#pragma unroll
        for (int mf = 0; mf < 2; mf++)
#pragma unroll
            for (int nf = 0; nf < 8; nf++) {
                acc[mf][nf][0] += bv0[nf]; acc[mf][nf][1] += bv1[nf];
                acc[mf][nf][2] += bv0[nf]; acc[mf][nf][3] += bv1[nf];
            }

        if (LSM) {
            float* sm_max = (float*)(smem + SM_A);
            float* sm_sum = (float*)(smem + SM_A + 1024);
            float mx[2][2], Mv[2][2], sv[2][2];
#pragma unroll
            for (int mf = 0; mf < 2; mf++)
#pragma unroll
                for (int ri = 0; ri < 2; ri++) {
                    float m = -1e30f;
#pragma unroll
                    for (int nf = 0; nf < 8; nf++) {
                        m = fmaxf(m, acc[mf][nf][ri * 2]);
                        m = fmaxf(m, acc[mf][nf][ri * 2 + 1]);
                    }
                    m = fmaxf(m, __shfl_xor_sync(0xFFFFFFFFu, m, 1));
                    m = fmaxf(m, __shfl_xor_sync(0xFFFFFFFFu, m, 2));
                    mx[mf][ri] = m;
                }
            if ((lane & 3) == 0) {
#pragma unroll
                for (int mf = 0; mf < 2; mf++)
#pragma unroll
                    for (int ri = 0; ri < 2; ri++) {
                        int rowl = warp_m * 32 + mf * 16 + ri * 8 + (lane >> 2);
                        sm_max[rowl * 2 + warp_n] = mx[mf][ri];
                    }
            }
            __syncthreads();
#pragma unroll
            for (int mf = 0; mf < 2; mf++)
#pragma unroll
                for (int ri = 0; ri < 2; ri++) {
                    int rowl = warp_m * 32 + mf * 16 + ri * 8 + (lane >> 2);
                    float m = fmaxf(sm_max[rowl * 2], sm_max[rowl * 2 + 1]);
                    Mv[mf][ri] = m;
                    float s = 0.f;
#pragma unroll
                    for (int nf = 0; nf < 8; nf++)
                        s += expf(acc[mf][nf][ri * 2] - m) + expf(acc[mf][nf][ri * 2 + 1] - m);
                    s += __shfl_xor_sync(0xFFFFFFFFu, s, 1);
                    s += __shfl_xor_sync(0xFFFFFFFFu, s, 2);
                    sv[mf][ri] = s;
                }
            if ((lane & 3) == 0) {
#pragma unroll
                for (int mf = 0; mf < 2; mf++)
#pragma unroll
                    for (int ri = 0; ri < 2; ri++) {
                        int rowl = warp_m * 32 + mf * 16 + ri * 8 + (lane >> 2);
                        sm_sum[rowl * 2 + warp_n] = sv[mf][ri];
                    }
            }
            __syncthreads();
#pragma unroll
            for (int mf = 0; mf < 2; mf++)
#pragma unroll
                for (int ri = 0; ri < 2; ri++) {
                    int rowl = warp_m * 32 + mf * 16 + ri * 8 + (lane >> 2);
                    float S = sm_sum[rowl * 2] + sm_sum[rowl * 2 + 1];
                    float lg = Mv[mf][ri] + logf(S);
                    int row = blockRow + rowl;
                    if (row < M) {
#pragma unroll
                        for (int nf = 0; nf < 8; nf++) {
                            int col = colbase + nf * 8 + (lane & 3) * 2;
                            *(float2*)(C + (size_t)row * Ncols + col) =
                                make_float2(acc[mf][nf][ri * 2] - lg, acc[mf][nf][ri * 2 + 1] - lg);
                        }
                    }
                }
        } else {
#pragma unroll
            for (int mf = 0; mf < 2; mf++) {
                int r0 = blockRow + warp_m * 32 + mf * 16 + (lane >> 2);
                int r1 = r0 + 8;
#pragma unroll
                for (int nf = 0; nf < 8; nf++) {
                    int col = colbase + nf * 8 + (lane & 3) * 2;
                    float o0 = acc[mf][nf][0], o1 = acc[mf][nf][1];
                    float o2 = acc[mf][nf][2], o3 = acc[mf][nf][3];
                    if (RELU) {
                        o0 = fmaxf(o0, 0.f); o1 = fmaxf(o1, 0.f);
                        o2 = fmaxf(o2, 0.f); o3 = fmaxf(o3, 0.f);
                    }
                    if (SPLIT) {
                        unsigned short h0, l0, h1, l1;
                        if (r0 < M) {
                            split1(o0, h0, l0); split1(o1, h1, l1);
                            *(uint32_t*)(Chi + (size_t)r0 * Ncols + col) = (uint32_t)h0 | ((uint32_t)h1 << 16);
                            *(uint32_t*)(Clo + (size_t)r0 * Ncols + col) = (uint32_t)l0 | ((uint32_t)l1 << 16);
                        }
                        if (r1 < M) {
                            split1(o2, h0, l0); split1(o3, h1, l1);
                            *(uint32_t*)(Chi + (size_t)r1 * Ncols + col) = (uint32_t)h0 | ((uint32_t)h1 << 16);
                            *(uint32_t*)(Clo + (size_t)r1 * Ncols + col) = (uint32_t)l0 | ((uint32_t)l1 << 16);
                        }
                    } else {
                        if (r0 < M) *(float2*)(C + (size_t)r0 * Ncols + col) = make_float2(o0, o1);
                        if (r1 < M) *(float2*)(C + (size_t)r1 * Ncols + col) = make_float2(o2, o3);
                    }
                }
            }
        }
    }
}

// ---------------- host launch -------------------------------------------------
extern "C" void kernel_launch(void* const* d_in, const int* in_sizes, int n_in,
                              void* d_out, int out_size) {
    const float* x    = (const float*)d_in[0];
    const void*  ei   = d_in[1];
    const float* eps0 = (const float*)d_in[2];
    const float* W1_0 = (const float*)d_in[3];
    const float* b1_0 = (const float*)d_in[4];
    const float* W2_0 = (const float*)d_in[5];
    const float* b2_0 = (const float*)d_in[6];
    const float* eps1 = (const float*)d_in[7];
    const float* W1_1 = (const float*)d_in[8];
    const float* b1_1 = (const float*)d_in[9];
    const float* W2_1 = (const float*)d_in[10];
    const float* b2_1 = (const float*)d_in[11];
    float* out = (float*)d_out;

    int E = in_sizes[1] / 2;
    if (E > EE) E = EE;
    int M = in_sizes[0] / INC;
    if (M > NN) M = NN;

    __nv_bfloat16 *xhi, *xlo, *mhi, *mlo, *whi, *wlo;
    float* h1;
    cudaGetSymbolAddress((void**)&xhi, g_xhi);
    cudaGetSymbolAddress((void**)&xlo, g_xlo);
    cudaGetSymbolAddress((void**)&mhi, g_mhi);
    cudaGetSymbolAddress((void**)&mlo, g_mlo);
    cudaGetSymbolAddress((void**)&h1,  g_h1);
    cudaGetSymbolAddress((void**)&whi, g_wt_hi);
    cudaGetSymbolAddress((void**)&wlo, g_wt_lo);

    cudaFuncSetAttribute(gemm_mma<1, 1, 0>, cudaFuncAttributeMaxDynamicSharedMemorySize, SM_TOTAL);
    cudaFuncSetAttribute(gemm_mma<1, 0, 0>, cudaFuncAttributeMaxDynamicSharedMemorySize, SM_TOTAL);
    cudaFuncSetAttribute(gemm_mma<0, 0, 1>, cudaFuncAttributeMaxDynamicSharedMemorySize, SM_TOTAL);

    const int egrid = (E + 255) / 256;
    const int ngrid = (M + 255) / 256;
    const int ggrid = (M + 7) / 8;
    const int mtiles = (M + 127) / 128;
    const dim3 grid_h(74, 2);      // persistent: 148 CTAs = 1 full wave
    const dim3 grid_o(148, 1);
    const int WSZ = 256 * 256;

    // ---- CSR build ----
    detzero_k<<<ngrid, 256>>>((const unsigned int*)ei);
    decode_hist_k<<<egrid, 256>>>(ei, E);
    block_sum_k<<<ngrid, 256>>>(M);
    scan_bsums_k<<<1, 256>>>(ngrid);
    rowptr_k<<<ngrid, 256>>>(M);
    fill_k<<<egrid, 256>>>(E);

    // ---- weight transpose + split (single launch) ----
    tw_all_k<<<dim3(256, 4), 256>>>(W1_0, W2_0, W1_1, W2_1);

    // ---- layer 0 ----
    gather_k<<<ggrid, 256>>>((const float4*)x, eps0, xhi, xlo, M);
    gemm_mma<1, 1, 0><<<grid_h, 256, SM_TOTAL>>>(xhi, xlo, whi + 0 * WSZ, wlo + 0 * WSZ,
                                                 b1_0, nullptr, mhi, mlo, M, HID, mtiles);
    gemm_mma<1, 0, 0><<<grid_h, 256, SM_TOTAL>>>(mhi, mlo, whi + 1 * WSZ, wlo + 1 * WSZ,
                                                 b2_0, h1, nullptr, nullptr, M, HID, mtiles);

    // ---- layer 1 ----
    gather_k<<<ggrid, 256>>>((const float4*)h1, eps1, xhi, xlo, M);
    gemm_mma<1, 1, 0><<<grid_h, 256, SM_TOTAL>>>(xhi, xlo, whi + 2 * WSZ, wlo + 2 * WSZ,
                                                 b1_1, nullptr, mhi, mlo, M, HID, mtiles);
    // final GEMM with fused log_softmax
    gemm_mma<0, 0, 1><<<grid_o, 256, SM_TOTAL>>>(mhi, mlo, whi + 3 * WSZ, wlo + 3 * WSZ,
                                                 b2_1, out, nullptr, nullptr, M, OUTC, mtiles);
}